// round 1
// baseline (speedup 1.0000x reference)
#include <cuda_runtime.h>
#include <cuda_bf16.h>
#include <math.h>

// ---------------------------------------------------------------------------
// BitNetAttention: B=2, S=2048, HID=1024, NH=16, HD=64
// out[4096*1024] fp32  +  out_scale (1 float) appended if out_size allows.
// ---------------------------------------------------------------------------

#define Bsz   2
#define Ssz   2048
#define HID   1024
#define NH    16
#define HD    64
#define MROWS (Bsz * Ssz)            // 4096
#define WELEM (HID * HID)            // 1048576

// ------------------------- device scratch ----------------------------------
__device__ double g_wsum[4];
__device__ float  g_scale[4];
__device__ float  g_wq[4 * WELEM];                 // quantized weights (fp32 values in {-1,0,1})
__device__ float  g_qkv[3 * MROWS * HID];          // q, k, v in [m][h*64+d] layout
__device__ float  g_ctx[MROWS * HID];              // attention output, same layout
__device__ float  g_cos[Ssz * 32];                 // [pos][d2]
__device__ float  g_sin[Ssz * 32];

// ------------------------- init / reductions -------------------------------
__global__ void k_init() {
    int t = threadIdx.x;
    if (t < 4) g_wsum[t] = 0.0;
}

__global__ __launch_bounds__(256) void k_abssum(const float* __restrict__ w0,
                                                const float* __restrict__ w1,
                                                const float* __restrict__ w2,
                                                const float* __restrict__ w3) {
    const int y = blockIdx.y;
    const float* w = (y == 0) ? w0 : (y == 1) ? w1 : (y == 2) ? w2 : w3;
    float s = 0.f;
    const int n4 = WELEM / 4;
    for (int i = blockIdx.x * blockDim.x + threadIdx.x; i < n4; i += gridDim.x * blockDim.x) {
        float4 v = ((const float4*)w)[i];
        s += fabsf(v.x) + fabsf(v.y) + fabsf(v.z) + fabsf(v.w);
    }
    #pragma unroll
    for (int o = 16; o; o >>= 1) s += __shfl_xor_sync(0xffffffffu, s, o);
    __shared__ float red[8];
    int wid = threadIdx.x >> 5;
    if ((threadIdx.x & 31) == 0) red[wid] = s;
    __syncthreads();
    if (threadIdx.x < 8) {
        s = red[threadIdx.x];
        #pragma unroll
        for (int o = 4; o; o >>= 1) s += __shfl_xor_sync(0xffu, s, o);
        if (threadIdx.x == 0) atomicAdd(&g_wsum[y], (double)s);
    }
}

__global__ void k_scales() {
    int t = threadIdx.x;
    if (t < 4) {
        float mean = (float)(g_wsum[t] * (1.0 / (double)WELEM));
        g_scale[t] = mean + 1e-5f;
    }
}

// trig table: cos/sin of fp32(pos * inv_freq) evaluated in double (fast-math safe,
// matches correctly-rounded reference bits as closely as possible).
__global__ __launch_bounds__(256) void k_trig() {
    int idx = blockIdx.x * blockDim.x + threadIdx.x;   // 2048*32
    if (idx >= Ssz * 32) return;
    int pos = idx >> 5;
    int d2  = idx & 31;
    // inv_freq = 1 / (10000 ** ((2*d2)/64)) computed as fp32 values
    float e = (float)(2 * d2) / 64.0f;                 // exact in fp32
    float t = (float)pow(10000.0, (double)e);          // correctly-rounded fp32 pow
    float invf = __frcp_rn(t);
    float f = __fmul_rn((float)pos, invf);             // fp32 product, like reference
    double sd, cd;
    sincos((double)f, &sd, &cd);
    g_cos[idx] = (float)cd;
    g_sin[idx] = (float)sd;
}

__global__ __launch_bounds__(256) void k_quant(const float* __restrict__ w0,
                                               const float* __restrict__ w1,
                                               const float* __restrict__ w2,
                                               const float* __restrict__ w3) {
    const int y = blockIdx.y;
    const float* w = (y == 0) ? w0 : (y == 1) ? w1 : (y == 2) ? w2 : w3;
    float* q = g_wq + (size_t)y * WELEM;
    const float s = g_scale[y];
    const int n4 = WELEM / 4;
    for (int i = blockIdx.x * blockDim.x + threadIdx.x; i < n4; i += gridDim.x * blockDim.x) {
        float4 v = ((const float4*)w)[i];
        float4 r;
        r.x = fminf(1.f, fmaxf(-1.f, rintf(__fdiv_rn(v.x, s))));
        r.y = fminf(1.f, fmaxf(-1.f, rintf(__fdiv_rn(v.y, s))));
        r.z = fminf(1.f, fmaxf(-1.f, rintf(__fdiv_rn(v.z, s))));
        r.w = fminf(1.f, fmaxf(-1.f, rintf(__fdiv_rn(v.w, s))));
        ((float4*)q)[i] = r;
    }
}

// ------------------------- SGEMM:  C[M][N] = A[M][K] * B[N][K]^T -----------
// BM=BN=128, BK=16, 256 threads, 8x8 per thread.
__global__ __launch_bounds__(256) void k_sgemm(const float* __restrict__ A,
                                               const float* __restrict__ B,
                                               float* __restrict__ C,
                                               int M, int N, int K) {
    __shared__ float As[16][132];
    __shared__ float Bs[16][132];
    const int tid  = threadIdx.x;
    const int lrow = tid >> 2;           // 0..63
    const int lcol = (tid & 3) << 2;     // 0,4,8,12
    const int ty = tid >> 4, tx = tid & 15;
    const int ri0 = ty << 2, ri1 = 64 + (ty << 2);
    const int cj0 = tx << 2, cj1 = 64 + (tx << 2);
    const float* Ab = A + (size_t)blockIdx.y * 128 * K;
    const float* Bb = B + (size_t)blockIdx.x * 128 * K;

    float acc[8][8];
    #pragma unroll
    for (int i = 0; i < 8; i++)
        #pragma unroll
        for (int j = 0; j < 8; j++) acc[i][j] = 0.f;

    for (int k0 = 0; k0 < K; k0 += 16) {
        float4 a0 = *(const float4*)(Ab + (size_t)lrow * K + k0 + lcol);
        float4 a1 = *(const float4*)(Ab + (size_t)(lrow + 64) * K + k0 + lcol);
        float4 b0 = *(const float4*)(Bb + (size_t)lrow * K + k0 + lcol);
        float4 b1 = *(const float4*)(Bb + (size_t)(lrow + 64) * K + k0 + lcol);
        __syncthreads();
        As[lcol + 0][lrow] = a0.x; As[lcol + 1][lrow] = a0.y;
        As[lcol + 2][lrow] = a0.z; As[lcol + 3][lrow] = a0.w;
        As[lcol + 0][lrow + 64] = a1.x; As[lcol + 1][lrow + 64] = a1.y;
        As[lcol + 2][lrow + 64] = a1.z; As[lcol + 3][lrow + 64] = a1.w;
        Bs[lcol + 0][lrow] = b0.x; Bs[lcol + 1][lrow] = b0.y;
        Bs[lcol + 2][lrow] = b0.z; Bs[lcol + 3][lrow] = b0.w;
        Bs[lcol + 0][lrow + 64] = b1.x; Bs[lcol + 1][lrow + 64] = b1.y;
        Bs[lcol + 2][lrow + 64] = b1.z; Bs[lcol + 3][lrow + 64] = b1.w;
        __syncthreads();
        #pragma unroll
        for (int kk = 0; kk < 16; kk++) {
            float ar[8], br[8];
            *(float4*)(ar)     = *(const float4*)&As[kk][ri0];
            *(float4*)(ar + 4) = *(const float4*)&As[kk][ri1];
            *(float4*)(br)     = *(const float4*)&Bs[kk][cj0];
            *(float4*)(br + 4) = *(const float4*)&Bs[kk][cj1];
            #pragma unroll
            for (int i = 0; i < 8; i++)
                #pragma unroll
                for (int j = 0; j < 8; j++)
                    acc[i][j] += ar[i] * br[j];
        }
    }
    #pragma unroll
    for (int i = 0; i < 8; i++) {
        int r = blockIdx.y * 128 + ((i < 4) ? (ri0 + i) : (ri1 + i - 4));
        float* Cp = C + (size_t)r * N + blockIdx.x * 128;
        *(float4*)(Cp + cj0) = make_float4(acc[i][0], acc[i][1], acc[i][2], acc[i][3]);
        *(float4*)(Cp + cj1) = make_float4(acc[i][4], acc[i][5], acc[i][6], acc[i][7]);
    }
}

// ------------------------- RoPE (in place, table-based) --------------------
__global__ __launch_bounds__(256) void k_rope(float* __restrict__ Qg,
                                              float* __restrict__ Kg,
                                              const int* __restrict__ pos_ids) {
    int idx = blockIdx.x * blockDim.x + threadIdx.x;   // 4096 * 16 * 32
    if (idx >= MROWS * NH * 32) return;
    int m  = idx >> 9;
    int hp = idx & 511;
    int h  = hp >> 5;
    int d2 = hp & 31;
    int p = pos_ids[m];
    p = (p < 0) ? 0 : ((p >= Ssz) ? Ssz - 1 : p);
    float cs = g_cos[p * 32 + d2];
    float sn = g_sin[p * 32 + d2];
    size_t base = (size_t)m * HID + h * HD + d2;
    float q1 = Qg[base], q2 = Qg[base + 32];
    Qg[base]      = q1 * cs - q2 * sn;
    Qg[base + 32] = q2 * cs + q1 * sn;
    float k1 = Kg[base], k2 = Kg[base + 32];
    Kg[base]      = k1 * cs - k2 * sn;
    Kg[base + 32] = k2 * cs + k1 * sn;
}

// ------------------------- attention (fp32, online softmax) ----------------
// BM=64 queries, BN=32 keys per iter. 256 threads as 16x16.
// Output written directly in [b, s, h*64+d] layout (no transpose needed).
__global__ __launch_bounds__(256) void k_attn(const float* __restrict__ Qg,
                                              const float* __restrict__ Kg,
                                              const float* __restrict__ Vg,
                                              float* __restrict__ Og) {
    __shared__ float Qs[64][68];
    __shared__ float Ks[32][68];
    __shared__ float Vs[32][68];
    __shared__ float Ps[64][36];
    const int tid = threadIdx.x;
    const int bh = blockIdx.y;
    const int b = bh >> 4, h = bh & 15;
    const int q0 = blockIdx.x * 64;
    const size_t rowbase = (size_t)b * Ssz * HID + (size_t)h * HD;

    for (int t = tid; t < 1024; t += 256) {
        int r = t >> 4, c = (t & 15) << 2;
        *(float4*)&Qs[r][c] = *(const float4*)(Qg + rowbase + (size_t)(q0 + r) * HID + c);
    }

    const int ty = tid >> 4, tx = tid & 15;
    const int i0 = ty << 2;        // 4 query rows
    const int cj = tx << 2;        // 4 output dims
    const int j0 = tx << 1;        // 2 key cols

    float m_i[4], l_i[4], o[4][4];
    #pragma unroll
    for (int i = 0; i < 4; i++) {
        m_i[i] = -3.0e38f; l_i[i] = 0.f;
        #pragma unroll
        for (int d = 0; d < 4; d++) o[i][d] = 0.f;
    }

    for (int kt = 0; kt < Ssz; kt += 32) {
        __syncthreads();
        for (int t = tid; t < 512; t += 256) {
            int r = t >> 4, c = (t & 15) << 2;
            size_t g = rowbase + (size_t)(kt + r) * HID + c;
            *(float4*)&Ks[r][c] = *(const float4*)(Kg + g);
            *(float4*)&Vs[r][c] = *(const float4*)(Vg + g);
        }
        __syncthreads();

        float s[4][2];
        #pragma unroll
        for (int i = 0; i < 4; i++) { s[i][0] = 0.f; s[i][1] = 0.f; }
        #pragma unroll
        for (int kk = 0; kk < 64; kk += 4) {
            float4 qv0 = *(const float4*)&Qs[i0 + 0][kk];
            float4 qv1 = *(const float4*)&Qs[i0 + 1][kk];
            float4 qv2 = *(const float4*)&Qs[i0 + 2][kk];
            float4 qv3 = *(const float4*)&Qs[i0 + 3][kk];
            float4 kv0 = *(const float4*)&Ks[j0 + 0][kk];
            float4 kv1 = *(const float4*)&Ks[j0 + 1][kk];
            s[0][0] += qv0.x*kv0.x + qv0.y*kv0.y + qv0.z*kv0.z + qv0.w*kv0.w;
            s[0][1] += qv0.x*kv1.x + qv0.y*kv1.y + qv0.z*kv1.z + qv0.w*kv1.w;
            s[1][0] += qv1.x*kv0.x + qv1.y*kv0.y + qv1.z*kv0.z + qv1.w*kv0.w;
            s[1][1] += qv1.x*kv1.x + qv1.y*kv1.y + qv1.z*kv1.z + qv1.w*kv1.w;
            s[2][0] += qv2.x*kv0.x + qv2.y*kv0.y + qv2.z*kv0.z + qv2.w*kv0.w;
            s[2][1] += qv2.x*kv1.x + qv2.y*kv1.y + qv2.z*kv1.z + qv2.w*kv1.w;
            s[3][0] += qv3.x*kv0.x + qv3.y*kv0.y + qv3.z*kv0.z + qv3.w*kv0.w;
            s[3][1] += qv3.x*kv1.x + qv3.y*kv1.y + qv3.z*kv1.z + qv3.w*kv1.w;
        }
        #pragma unroll
        for (int i = 0; i < 4; i++) {
            float s0 = s[i][0] * 0.125f, s1 = s[i][1] * 0.125f;
            float mx = fmaxf(s0, s1);
            #pragma unroll
            for (int off = 8; off; off >>= 1)
                mx = fmaxf(mx, __shfl_xor_sync(0xffffffffu, mx, off));
            float mnew = fmaxf(m_i[i], mx);
            float corr = __expf(m_i[i] - mnew);
            float p0 = __expf(s0 - mnew), p1 = __expf(s1 - mnew);
            float rs = p0 + p1;
            #pragma unroll
            for (int off = 8; off; off >>= 1)
                rs += __shfl_xor_sync(0xffffffffu, rs, off);
            l_i[i] = l_i[i] * corr + rs;
            m_i[i] = mnew;
            #pragma unroll
            for (int d = 0; d < 4; d++) o[i][d] *= corr;
            Ps[i0 + i][j0] = p0; Ps[i0 + i][j0 + 1] = p1;
        }
        __syncthreads();
        #pragma unroll
        for (int j = 0; j < 32; j += 4) {
            float4 pv0 = *(const float4*)&Ps[i0 + 0][j];
            float4 pv1 = *(const float4*)&Ps[i0 + 1][j];
            float4 pv2 = *(const float4*)&Ps[i0 + 2][j];
            float4 pv3 = *(const float4*)&Ps[i0 + 3][j];
            float4 vv0 = *(const float4*)&Vs[j + 0][cj];
            float4 vv1 = *(const float4*)&Vs[j + 1][cj];
            float4 vv2 = *(const float4*)&Vs[j + 2][cj];
            float4 vv3 = *(const float4*)&Vs[j + 3][cj];
            o[0][0] += pv0.x*vv0.x + pv0.y*vv1.x + pv0.z*vv2.x + pv0.w*vv3.x;
            o[0][1] += pv0.x*vv0.y + pv0.y*vv1.y + pv0.z*vv2.y + pv0.w*vv3.y;
            o[0][2] += pv0.x*vv0.z + pv0.y*vv1.z + pv0.z*vv2.z + pv0.w*vv3.z;
            o[0][3] += pv0.x*vv0.w + pv0.y*vv1.w + pv0.z*vv2.w + pv0.w*vv3.w;
            o[1][0] += pv1.x*vv0.x + pv1.y*vv1.x + pv1.z*vv2.x + pv1.w*vv3.x;
            o[1][1] += pv1.x*vv0.y + pv1.y*vv1.y + pv1.z*vv2.y + pv1.w*vv3.y;
            o[1][2] += pv1.x*vv0.z + pv1.y*vv1.z + pv1.z*vv2.z + pv1.w*vv3.z;
            o[1][3] += pv1.x*vv0.w + pv1.y*vv1.w + pv1.z*vv2.w + pv1.w*vv3.w;
            o[2][0] += pv2.x*vv0.x + pv2.y*vv1.x + pv2.z*vv2.x + pv2.w*vv3.x;
            o[2][1] += pv2.x*vv0.y + pv2.y*vv1.y + pv2.z*vv2.y + pv2.w*vv3.y;
            o[2][2] += pv2.x*vv0.z + pv2.y*vv1.z + pv2.z*vv2.z + pv2.w*vv3.z;
            o[2][3] += pv2.x*vv0.w + pv2.y*vv1.w + pv2.z*vv2.w + pv2.w*vv3.w;
            o[3][0] += pv3.x*vv0.x + pv3.y*vv1.x + pv3.z*vv2.x + pv3.w*vv3.x;
            o[3][1] += pv3.x*vv0.y + pv3.y*vv1.y + pv3.z*vv2.y + pv3.w*vv3.y;
            o[3][2] += pv3.x*vv0.z + pv3.y*vv1.z + pv3.z*vv2.z + pv3.w*vv3.z;
            o[3][3] += pv3.x*vv0.w + pv3.y*vv1.w + pv3.z*vv2.w + pv3.w*vv3.w;
        }
    }
    #pragma unroll
    for (int i = 0; i < 4; i++) {
        float inv = 1.0f / l_i[i];
        float4 w = make_float4(o[i][0]*inv, o[i][1]*inv, o[i][2]*inv, o[i][3]*inv);
        *(float4*)(Og + rowbase + (size_t)(q0 + i0 + i) * HID + cj) = w;
    }
}

// ------------------------- out_scale ---------------------------------------
__global__ void k_out_scale(const float* __restrict__ hss, float* __restrict__ out, int out_size) {
    if (out_size >= MROWS * HID + 1) {
        // out_scale = ((hs_scale * sv) * so)  -- left-assoc like the reference
        out[MROWS * HID] = (hss[0] * g_scale[2]) * g_scale[3];
    }
}

// ------------------------- launch ------------------------------------------
extern "C" void kernel_launch(void* const* d_in, const int* in_sizes, int n_in,
                              void* d_out, int out_size) {
    const float* hs  = (const float*)d_in[0];
    const float* hss = (const float*)d_in[1];
    const int*   pos = (const int*)d_in[2];
    const float* wq  = (const float*)d_in[3];
    const float* wk  = (const float*)d_in[4];
    const float* wv  = (const float*)d_in[5];
    const float* wo  = (const float*)d_in[6];
    float* out = (float*)d_out;

    float *p_wq, *p_qkv, *p_ctx;
    cudaGetSymbolAddress((void**)&p_wq,  g_wq);
    cudaGetSymbolAddress((void**)&p_qkv, g_qkv);
    cudaGetSymbolAddress((void**)&p_ctx, g_ctx);

    float* qf = p_qkv + 0 * (size_t)MROWS * HID;
    float* kf = p_qkv + 1 * (size_t)MROWS * HID;
    float* vf = p_qkv + 2 * (size_t)MROWS * HID;

    k_init<<<1, 32>>>();
    k_abssum<<<dim3(64, 4), 256>>>(wq, wk, wv, wo);
    k_scales<<<1, 32>>>();
    k_trig<<<(Ssz * 32 + 255) / 256, 256>>>();
    k_quant<<<dim3(64, 4), 256>>>(wq, wk, wv, wo);

    dim3 gproj(HID / 128, MROWS / 128);   // (8, 32)
    k_sgemm<<<gproj, 256>>>(hs, p_wq + 0 * (size_t)WELEM, qf, MROWS, HID, HID);
    k_sgemm<<<gproj, 256>>>(hs, p_wq + 1 * (size_t)WELEM, kf, MROWS, HID, HID);
    k_sgemm<<<gproj, 256>>>(hs, p_wq + 2 * (size_t)WELEM, vf, MROWS, HID, HID);

    k_rope<<<(MROWS * NH * 32 + 255) / 256, 256>>>(qf, kf, pos);

    k_attn<<<dim3(Ssz / 64, Bsz * NH), 256>>>(qf, kf, vf, p_ctx);

    k_sgemm<<<gproj, 256>>>(p_ctx, p_wq + 3 * (size_t)WELEM, out, MROWS, HID, HID);

    k_out_scale<<<1, 1>>>(hss, out, out_size);
}

// round 9
// speedup vs baseline: 1.0611x; 1.0611x over previous
#include <cuda_runtime.h>
#include <cuda_bf16.h>
#include <mma.h>
#include <math.h>

// ---------------------------------------------------------------------------
// BitNetAttention: B=2, S=2048, HID=1024, NH=16, HD=64
// Projections on bf16 tensor cores via the wmma intrinsic API (no inline asm,
// no template declarations, no uint32_t -- toolchain/header quirks).
// Exact 3-plane bf16 split of fp32 activations; ternary weights are exact in
// bf16. Attention in fp32 (round-1 verbatim).
// ---------------------------------------------------------------------------

#define Bsz   2
#define Ssz   2048
#define HID   1024
#define NH    16
#define HD    64
#define MROWS (Bsz * Ssz)
#define WELEM (HID * HID)
#define PLANE ((size_t)MROWS * HID)

namespace wx = nvcuda::wmma;

__device__ double g_wsum[4];
__device__ float  g_scale[4];
__device__ __nv_bfloat16 g_wb[4 * WELEM];
__device__ __nv_bfloat16 g_pl[3 * MROWS * HID];
__device__ float  g_qkv[3 * MROWS * HID];
__device__ float  g_ctx[MROWS * HID];
__device__ float  g_cos[Ssz * 32];
__device__ float  g_sin[Ssz * 32];

// ------------------------- init / scale / trig / quant ---------------------
__global__ void k_init() {
    if (threadIdx.x < 4) g_wsum[threadIdx.x] = 0.0;
}

__global__ __launch_bounds__(256) void k_abssum(const float* __restrict__ w0,
                                                const float* __restrict__ w1,
                                                const float* __restrict__ w2,
                                                const float* __restrict__ w3) {
    const int y = blockIdx.y;
    const float* w = (y == 0) ? w0 : (y == 1) ? w1 : (y == 2) ? w2 : w3;
    float acc = 0.f;
    const int n4 = WELEM / 4;
    for (int i = blockIdx.x * blockDim.x + threadIdx.x; i < n4; i += gridDim.x * blockDim.x) {
        float4 v = ((const float4*)w)[i];
        acc += fabsf(v.x) + fabsf(v.y) + fabsf(v.z) + fabsf(v.w);
    }
    for (int o = 16; o; o >>= 1) acc += __shfl_xor_sync(0xffffffffu, acc, o);
    __shared__ float red[8];
    if ((threadIdx.x & 31) == 0) red[threadIdx.x >> 5] = acc;
    __syncthreads();
    if (threadIdx.x < 8) {
        acc = red[threadIdx.x];
        for (int o = 4; o; o >>= 1) acc += __shfl_xor_sync(0xffu, acc, o);
        if (threadIdx.x == 0) atomicAdd(&g_wsum[y], (double)acc);
    }
}

__global__ void k_scales() {
    if (threadIdx.x < 4) {
        float mean = (float)(g_wsum[threadIdx.x] * (1.0 / (double)WELEM));
        g_scale[threadIdx.x] = mean + 1e-5f;
    }
}

__global__ __launch_bounds__(256) void k_trig() {
    int idx = blockIdx.x * blockDim.x + threadIdx.x;
    if (idx >= Ssz * 32) return;
    int pos = idx >> 5;
    int d2  = idx & 31;
    float e = (float)(2 * d2) / 64.0f;
    float t = (float)pow(10000.0, (double)e);
    float invf = __frcp_rn(t);
    float f = __fmul_rn((float)pos, invf);
    double sd, cd;
    sincos((double)f, &sd, &cd);
    g_cos[idx] = (float)cd;
    g_sin[idx] = (float)sd;
}

__global__ __launch_bounds__(256) void k_quant(const float* __restrict__ w0,
                                               const float* __restrict__ w1,
                                               const float* __restrict__ w2,
                                               const float* __restrict__ w3) {
    const int y = blockIdx.y;
    const float* w = (y == 0) ? w0 : (y == 1) ? w1 : (y == 2) ? w2 : w3;
    __nv_bfloat16* q = g_wb + (size_t)y * WELEM;
    const float sc = g_scale[y];
    const int n4 = WELEM / 4;
    for (int i = blockIdx.x * blockDim.x + threadIdx.x; i < n4; i += gridDim.x * blockDim.x) {
        float4 v = ((const float4*)w)[i];
        float r0 = fminf(1.f, fmaxf(-1.f, rintf(__fdiv_rn(v.x, sc))));
        float r1 = fminf(1.f, fmaxf(-1.f, rintf(__fdiv_rn(v.y, sc))));
        float r2 = fminf(1.f, fmaxf(-1.f, rintf(__fdiv_rn(v.z, sc))));
        float r3 = fminf(1.f, fmaxf(-1.f, rintf(__fdiv_rn(v.w, sc))));
        unsigned int lo = ((unsigned int)__bfloat16_as_ushort(__float2bfloat16_rn(r1)) << 16)
                        | (unsigned int)__bfloat16_as_ushort(__float2bfloat16_rn(r0));
        unsigned int hi = ((unsigned int)__bfloat16_as_ushort(__float2bfloat16_rn(r3)) << 16)
                        | (unsigned int)__bfloat16_as_ushort(__float2bfloat16_rn(r2));
        ((uint2*)q)[i] = make_uint2(lo, hi);
    }
}

// exact 3-plane split of fp32 into bf16 planes
__global__ __launch_bounds__(256) void k_split(const float* __restrict__ x) {
    int i = blockIdx.x * blockDim.x + threadIdx.x;
    if (i >= (MROWS * HID) / 4) return;
    float4 v = ((const float4*)x)[i];
    float xs[4];
    xs[0] = v.x; xs[1] = v.y; xs[2] = v.z; xs[3] = v.w;
    unsigned int w0[2], w1[2], w2[2];
    #pragma unroll
    for (int pair = 0; pair < 2; pair++) {
        unsigned int a0 = 0, a1 = 0, a2 = 0;
        #pragma unroll
        for (int e = 0; e < 2; e++) {
            float xv = xs[pair * 2 + e];
            __nv_bfloat16 h0 = __float2bfloat16_rn(xv);
            float r1 = __fsub_rn(xv, __bfloat162float(h0));
            __nv_bfloat16 h1 = __float2bfloat16_rn(r1);
            float r2 = __fsub_rn(r1, __bfloat162float(h1));
            __nv_bfloat16 h2 = __float2bfloat16_rn(r2);
            a0 |= (unsigned int)__bfloat16_as_ushort(h0) << (16 * e);
            a1 |= (unsigned int)__bfloat16_as_ushort(h1) << (16 * e);
            a2 |= (unsigned int)__bfloat16_as_ushort(h2) << (16 * e);
        }
        w0[pair] = a0; w1[pair] = a1; w2[pair] = a2;
    }
    ((uint2*)(g_pl + 0 * PLANE))[i] = make_uint2(w0[0], w0[1]);
    ((uint2*)(g_pl + 1 * PLANE))[i] = make_uint2(w1[0], w1[1]);
    ((uint2*)(g_pl + 2 * PLANE))[i] = make_uint2(w2[0], w2[1]);
}

// ------------------------- wmma bf16 GEMM ----------------------------------
// C[M][N] = sum over 3 planes of A_s[M][K] @ B[N][K]^T.
// CTA tile 128x128, BK=16, 8 warps as 4x2 (warp tile 32x64).
__global__ __launch_bounds__(256) void k_bgemm(const __nv_bfloat16* __restrict__ A,
                                               const __nv_bfloat16* __restrict__ B,
                                               float* __restrict__ C) {
    __shared__ __align__(16) __nv_bfloat16 sA[3][128][32];
    __shared__ __align__(16) __nv_bfloat16 sB[128][32];
    const int t = threadIdx.x;
    const int wid = t >> 5;
    const int wm = (wid >> 1) * 32;
    const int wn = (wid & 1) * 64;
    const int lrow = t >> 1;
    const int lcol = (t & 1) * 8;
    const __nv_bfloat16* ag = A + ((size_t)blockIdx.y * 128 + lrow) * HID + lcol;
    const __nv_bfloat16* bg = B + ((size_t)blockIdx.x * 128 + lrow) * HID + lcol;

    wx::fragment<wx::accumulator, 16, 16, 16, float> acc[2][4];
    #pragma unroll
    for (int i = 0; i < 2; i++)
        #pragma unroll
        for (int j = 0; j < 4; j++)
            wx::fill_fragment(acc[i][j], 0.0f);

    for (int k0 = 0; k0 < HID; k0 += 16) {
        __syncthreads();
        *(uint4*)&sA[0][lrow][lcol] = *(const uint4*)(ag + 0 * PLANE + k0);
        *(uint4*)&sA[1][lrow][lcol] = *(const uint4*)(ag + 1 * PLANE + k0);
        *(uint4*)&sA[2][lrow][lcol] = *(const uint4*)(ag + 2 * PLANE + k0);
        *(uint4*)&sB[lrow][lcol]    = *(const uint4*)(bg + k0);
        __syncthreads();

        wx::fragment<wx::matrix_b, 16, 16, 16, __nv_bfloat16, wx::col_major> bf[4];
        #pragma unroll
        for (int j = 0; j < 4; j++)
            wx::load_matrix_sync(bf[j], &sB[wn + 16 * j][0], 32);

        #pragma unroll
        for (int s = 0; s < 3; s++) {
            wx::fragment<wx::matrix_a, 16, 16, 16, __nv_bfloat16, wx::row_major> af[2];
            wx::load_matrix_sync(af[0], &sA[s][wm][0], 32);
            wx::load_matrix_sync(af[1], &sA[s][wm + 16][0], 32);
            #pragma unroll
            for (int i = 0; i < 2; i++)
                #pragma unroll
                for (int j = 0; j < 4; j++)
                    wx::mma_sync(acc[i][j], af[i], bf[j], acc[i][j]);
        }
    }

    #pragma unroll
    for (int i = 0; i < 2; i++)
        #pragma unroll
        for (int j = 0; j < 4; j++) {
            float* cp = C + ((size_t)blockIdx.y * 128 + wm + 16 * i) * HID
                          + blockIdx.x * 128 + wn + 16 * j;
            wx::store_matrix_sync(cp, acc[i][j], HID, wx::mem_row_major);
        }
}

// ------------------------- RoPE --------------------------------------------
__global__ __launch_bounds__(256) void k_rope(float* __restrict__ Qg,
                                              float* __restrict__ Kg,
                                              const int* __restrict__ pos_ids) {
    int idx = blockIdx.x * blockDim.x + threadIdx.x;
    if (idx >= MROWS * NH * 32) return;
    int m  = idx >> 9;
    int hp = idx & 511;
    int h  = hp >> 5;
    int d2 = hp & 31;
    int p = pos_ids[m];
    p = (p < 0) ? 0 : ((p >= Ssz) ? Ssz - 1 : p);
    float cs = g_cos[p * 32 + d2];
    float sn = g_sin[p * 32 + d2];
    size_t base = (size_t)m * HID + h * HD + d2;
    float q1 = Qg[base], q2 = Qg[base + 32];
    Qg[base]      = q1 * cs - q2 * sn;
    Qg[base + 32] = q2 * cs + q1 * sn;
    float k1 = Kg[base], k2 = Kg[base + 32];
    Kg[base]      = k1 * cs - k2 * sn;
    Kg[base + 32] = k2 * cs + k1 * sn;
}

// ------------------------- attention (fp32, online softmax) ----------------
__global__ __launch_bounds__(256) void k_attn(const float* __restrict__ Qg,
                                              const float* __restrict__ Kg,
                                              const float* __restrict__ Vg,
                                              float* __restrict__ Og) {
    __shared__ float Qs[64][68];
    __shared__ float Ks[32][68];
    __shared__ float Vs[32][68];
    __shared__ float Ps[64][36];
    const int tid = threadIdx.x;
    const int bh = blockIdx.y;
    const int b = bh >> 4, h = bh & 15;
    const int q0 = blockIdx.x * 64;
    const size_t rowbase = (size_t)b * Ssz * HID + (size_t)h * HD;

    for (int t = tid; t < 1024; t += 256) {
        int r = t >> 4, c = (t & 15) << 2;
        *(float4*)&Qs[r][c] = *(const float4*)(Qg + rowbase + (size_t)(q0 + r) * HID + c);
    }

    const int ty = tid >> 4, tx = tid & 15;
    const int i0 = ty << 2;
    const int cj = tx << 2;
    const int j0 = tx << 1;

    float m_i[4], l_i[4], o[4][4];
    #pragma unroll
    for (int i = 0; i < 4; i++) {
        m_i[i] = -3.0e38f; l_i[i] = 0.f;
        #pragma unroll
        for (int d = 0; d < 4; d++) o[i][d] = 0.f;
    }

    for (int kt = 0; kt < Ssz; kt += 32) {
        __syncthreads();
        for (int t = tid; t < 512; t += 256) {
            int r = t >> 4, c = (t & 15) << 2;
            size_t g = rowbase + (size_t)(kt + r) * HID + c;
            *(float4*)&Ks[r][c] = *(const float4*)(Kg + g);
            *(float4*)&Vs[r][c] = *(const float4*)(Vg + g);
        }
        __syncthreads();

        float s[4][2];
        #pragma unroll
        for (int i = 0; i < 4; i++) { s[i][0] = 0.f; s[i][1] = 0.f; }
        #pragma unroll
        for (int kk = 0; kk < 64; kk += 4) {
            float4 qv0 = *(const float4*)&Qs[i0 + 0][kk];
            float4 qv1 = *(const float4*)&Qs[i0 + 1][kk];
            float4 qv2 = *(const float4*)&Qs[i0 + 2][kk];
            float4 qv3 = *(const float4*)&Qs[i0 + 3][kk];
            float4 kv0 = *(const float4*)&Ks[j0 + 0][kk];
            float4 kv1 = *(const float4*)&Ks[j0 + 1][kk];
            s[0][0] += qv0.x*kv0.x + qv0.y*kv0.y + qv0.z*kv0.z + qv0.w*kv0.w;
            s[0][1] += qv0.x*kv1.x + qv0.y*kv1.y + qv0.z*kv1.z + qv0.w*kv1.w;
            s[1][0] += qv1.x*kv0.x + qv1.y*kv0.y + qv1.z*kv0.z + qv1.w*kv0.w;
            s[1][1] += qv1.x*kv1.x + qv1.y*kv1.y + qv1.z*kv1.z + qv1.w*kv1.w;
            s[2][0] += qv2.x*kv0.x + qv2.y*kv0.y + qv2.z*kv0.z + qv2.w*kv0.w;
            s[2][1] += qv2.x*kv1.x + qv2.y*kv1.y + qv2.z*kv1.z + qv2.w*kv1.w;
            s[3][0] += qv3.x*kv0.x + qv3.y*kv0.y + qv3.z*kv0.z + qv3.w*kv0.w;
            s[3][1] += qv3.x*kv1.x + qv3.y*kv1.y + qv3.z*kv1.z + qv3.w*kv1.w;
        }
        #pragma unroll
        for (int i = 0; i < 4; i++) {
            float s0 = s[i][0] * 0.125f, s1 = s[i][1] * 0.125f;
            float mx = fmaxf(s0, s1);
            #pragma unroll
            for (int off = 8; off; off >>= 1)
                mx = fmaxf(mx, __shfl_xor_sync(0xffffffffu, mx, off));
            float mnew = fmaxf(m_i[i], mx);
            float corr = __expf(m_i[i] - mnew);
            float p0 = __expf(s0 - mnew), p1 = __expf(s1 - mnew);
            float rs = p0 + p1;
            #pragma unroll
            for (int off = 8; off; off >>= 1)
                rs += __shfl_xor_sync(0xffffffffu, rs, off);
            l_i[i] = l_i[i] * corr + rs;
            m_i[i] = mnew;
            #pragma unroll
            for (int d = 0; d < 4; d++) o[i][d] *= corr;
            Ps[i0 + i][j0] = p0; Ps[i0 + i][j0 + 1] = p1;
        }
        __syncthreads();
        #pragma unroll
        for (int j = 0; j < 32; j += 4) {
            float4 pv0 = *(const float4*)&Ps[i0 + 0][j];
            float4 pv1 = *(const float4*)&Ps[i0 + 1][j];
            float4 pv2 = *(const float4*)&Ps[i0 + 2][j];
            float4 pv3 = *(const float4*)&Ps[i0 + 3][j];
            float4 vv0 = *(const float4*)&Vs[j + 0][cj];
            float4 vv1 = *(const float4*)&Vs[j + 1][cj];
            float4 vv2 = *(const float4*)&Vs[j + 2][cj];
            float4 vv3 = *(const float4*)&Vs[j + 3][cj];
            o[0][0] += pv0.x*vv0.x + pv0.y*vv1.x + pv0.z*vv2.x + pv0.w*vv3.x;
            o[0][1] += pv0.x*vv0.y + pv0.y*vv1.y + pv0.z*vv2.y + pv0.w*vv3.y;
            o[0][2] += pv0.x*vv0.z + pv0.y*vv1.z + pv0.z*vv2.z + pv0.w*vv3.z;
            o[0][3] += pv0.x*vv0.w + pv0.y*vv1.w + pv0.z*vv2.w + pv0.w*vv3.w;
            o[1][0] += pv1.x*vv0.x + pv1.y*vv1.x + pv1.z*vv2.x + pv1.w*vv3.x;
            o[1][1] += pv1.x*vv0.y + pv1.y*vv1.y + pv1.z*vv2.y + pv1.w*vv3.y;
            o[1][2] += pv1.x*vv0.z + pv1.y*vv1.z + pv1.z*vv2.z + pv1.w*vv3.z;
            o[1][3] += pv1.x*vv0.w + pv1.y*vv1.w + pv1.z*vv2.w + pv1.w*vv3.w;
            o[2][0] += pv2.x*vv0.x + pv2.y*vv1.x + pv2.z*vv2.x + pv2.w*vv3.x;
            o[2][1] += pv2.x*vv0.y + pv2.y*vv1.y + pv2.z*vv2.y + pv2.w*vv3.y;
            o[2][2] += pv2.x*vv0.z + pv2.y*vv1.z + pv2.z*vv2.z + pv2.w*vv3.z;
            o[2][3] += pv2.x*vv0.w + pv2.y*vv1.w + pv2.z*vv2.w + pv2.w*vv3.w;
            o[3][0] += pv3.x*vv0.x + pv3.y*vv1.x + pv3.z*vv2.x + pv3.w*vv3.x;
            o[3][1] += pv3.x*vv0.y + pv3.y*vv1.y + pv3.z*vv2.y + pv3.w*vv3.y;
            o[3][2] += pv3.x*vv0.z + pv3.y*vv1.z + pv3.z*vv2.z + pv3.w*vv3.z;
            o[3][3] += pv3.x*vv0.w + pv3.y*vv1.w + pv3.z*vv2.w + pv3.w*vv3.w;
        }
    }
    #pragma unroll
    for (int i = 0; i < 4; i++) {
        float inv = 1.0f / l_i[i];
        float4 w = make_float4(o[i][0]*inv, o[i][1]*inv, o[i][2]*inv, o[i][3]*inv);
        *(float4*)(Og + rowbase + (size_t)(q0 + i0 + i) * HID + cj) = w;
    }
}

// ------------------------- out_scale ---------------------------------------
__global__ void k_out_scale(const float* __restrict__ hss, float* __restrict__ out, int out_size) {
    if (out_size >= MROWS * HID + 1) {
        out[MROWS * HID] = (hss[0] * g_scale[2]) * g_scale[3];
    }
}

// ------------------------- launch ------------------------------------------
extern "C" void kernel_launch(void* const* d_in, const int* in_sizes, int n_in,
                              void* d_out, int out_size) {
    const float* hs  = (const float*)d_in[0];
    const float* hss = (const float*)d_in[1];
    const int*   pos = (const int*)d_in[2];
    const float* wq  = (const float*)d_in[3];
    const float* wk  = (const float*)d_in[4];
    const float* wv  = (const float*)d_in[5];
    const float* wo  = (const float*)d_in[6];
    float* out = (float*)d_out;

    __nv_bfloat16 *p_wb, *p_pl;
    float *p_qkv, *p_ctx;
    cudaGetSymbolAddress((void**)&p_wb,  g_wb);
    cudaGetSymbolAddress((void**)&p_pl,  g_pl);
    cudaGetSymbolAddress((void**)&p_qkv, g_qkv);
    cudaGetSymbolAddress((void**)&p_ctx, g_ctx);

    float* qf = p_qkv + 0 * PLANE;
    float* kf = p_qkv + 1 * PLANE;
    float* vf = p_qkv + 2 * PLANE;

    k_init<<<1, 32>>>();
    k_abssum<<<dim3(64, 4), 256>>>(wq, wk, wv, wo);
    k_scales<<<1, 32>>>();
    k_trig<<<(Ssz * 32 + 255) / 256, 256>>>();
    k_quant<<<dim3(64, 4), 256>>>(wq, wk, wv, wo);

    k_split<<<(MROWS * HID / 4 + 255) / 256, 256>>>(hs);

    dim3 gproj(HID / 128, MROWS / 128);
    k_bgemm<<<gproj, 256>>>(p_pl, p_wb + 0 * (size_t)WELEM, qf);
    k_bgemm<<<gproj, 256>>>(p_pl, p_wb + 1 * (size_t)WELEM, kf);
    k_bgemm<<<gproj, 256>>>(p_pl, p_wb + 2 * (size_t)WELEM, vf);

    k_rope<<<(MROWS * NH * 32 + 255) / 256, 256>>>(qf, kf, pos);

    k_attn<<<dim3(Ssz / 64, Bsz * NH), 256>>>(qf, kf, vf, p_ctx);

    k_split<<<(MROWS * HID / 4 + 255) / 256, 256>>>(p_ctx);
    k_bgemm<<<gproj, 256>>>(p_pl, p_wb + 3 * (size_t)WELEM, out);

    k_out_scale<<<1, 1>>>(hss, out, out_size);
}

// round 10
// speedup vs baseline: 1.3326x; 1.2559x over previous
#include <cuda_runtime.h>
#include <cuda_bf16.h>
#include <mma.h>
#include <math.h>

// ---------------------------------------------------------------------------
// BitNetAttention: B=2, S=2048, HID=1024, NH=16, HD=64
// Projections + attention scores on bf16 tensor cores (wmma API only: the
// bench pipeline mangles inline asm and template declarations; uint32_t is
// unavailable -- use unsigned int).
// Exact multi-plane bf16 splits make all tensor-core math equal to fp32 up
// to accumulation order. Softmax + P*V stay fp32.
// ---------------------------------------------------------------------------

#define Bsz   2
#define Ssz   2048
#define HID   1024
#define NH    16
#define HD    64
#define MROWS (Bsz * Ssz)
#define WELEM (HID * HID)
#define PLANE ((size_t)MROWS * HID)

namespace wx = nvcuda::wmma;

__device__ double g_part[4][64];
__device__ float  g_scale[4];
__device__ __nv_bfloat16 g_wb[4 * WELEM];
__device__ __nv_bfloat16 g_pl[3 * MROWS * HID];
__device__ __nv_bfloat16 g_qpl[3 * MROWS * HID];
__device__ __nv_bfloat16 g_kpl[3 * MROWS * HID];
__device__ float  g_qkv[3 * MROWS * HID];
__device__ float  g_ctx[MROWS * HID];
__device__ float  g_cos[Ssz * 32];
__device__ float  g_sin[Ssz * 32];

// ------------------------- abssum partials ---------------------------------
__global__ __launch_bounds__(256) void k_abssum(const float* __restrict__ w0,
                                                const float* __restrict__ w1,
                                                const float* __restrict__ w2,
                                                const float* __restrict__ w3) {
    const int y = blockIdx.y;
    const float* w = (y == 0) ? w0 : (y == 1) ? w1 : (y == 2) ? w2 : w3;
    float acc = 0.f;
    const int n4 = WELEM / 4;
    for (int i = blockIdx.x * blockDim.x + threadIdx.x; i < n4; i += gridDim.x * blockDim.x) {
        float4 v = ((const float4*)w)[i];
        acc += fabsf(v.x) + fabsf(v.y) + fabsf(v.z) + fabsf(v.w);
    }
    for (int o = 16; o; o >>= 1) acc += __shfl_xor_sync(0xffffffffu, acc, o);
    __shared__ float red[8];
    if ((threadIdx.x & 31) == 0) red[threadIdx.x >> 5] = acc;
    __syncthreads();
    if (threadIdx.x < 8) {
        acc = red[threadIdx.x];
        for (int o = 4; o; o >>= 1) acc += __shfl_xor_sync(0xffu, acc, o);
        if (threadIdx.x == 0) g_part[y][blockIdx.x] = (double)acc;
    }
}

// exact 3-plane split of fp32 into bf16 planes
__global__ __launch_bounds__(256) void k_split(const float* __restrict__ x) {
    int i = blockIdx.x * blockDim.x + threadIdx.x;
    if (i >= (MROWS * HID) / 4) return;
    float4 v = ((const float4*)x)[i];
    float xs[4];
    xs[0] = v.x; xs[1] = v.y; xs[2] = v.z; xs[3] = v.w;
    unsigned int w0[2], w1[2], w2[2];
    #pragma unroll
    for (int pair = 0; pair < 2; pair++) {
        unsigned int a0 = 0, a1 = 0, a2 = 0;
        #pragma unroll
        for (int e = 0; e < 2; e++) {
            float xv = xs[pair * 2 + e];
            __nv_bfloat16 h0 = __float2bfloat16_rn(xv);
            float r1 = __fsub_rn(xv, __bfloat162float(h0));
            __nv_bfloat16 h1 = __float2bfloat16_rn(r1);
            float r2 = __fsub_rn(r1, __bfloat162float(h1));
            __nv_bfloat16 h2 = __float2bfloat16_rn(r2);
            a0 |= (unsigned int)__bfloat16_as_ushort(h0) << (16 * e);
            a1 |= (unsigned int)__bfloat16_as_ushort(h1) << (16 * e);
            a2 |= (unsigned int)__bfloat16_as_ushort(h2) << (16 * e);
        }
        w0[pair] = a0; w1[pair] = a1; w2[pair] = a2;
    }
    ((uint2*)(g_pl + 0 * PLANE))[i] = make_uint2(w0[0], w0[1]);
    ((uint2*)(g_pl + 1 * PLANE))[i] = make_uint2(w1[0], w1[1]);
    ((uint2*)(g_pl + 2 * PLANE))[i] = make_uint2(w2[0], w2[1]);
}

// quantize; the absmean scale is reduced from partials at block start
__global__ __launch_bounds__(256) void k_quant(const float* __restrict__ w0,
                                               const float* __restrict__ w1,
                                               const float* __restrict__ w2,
                                               const float* __restrict__ w3) {
    const int y = blockIdx.y;
    const float* w = (y == 0) ? w0 : (y == 1) ? w1 : (y == 2) ? w2 : w3;
    __nv_bfloat16* q = g_wb + (size_t)y * WELEM;
    __shared__ float s_sc;
    if (threadIdx.x < 32) {
        double d = g_part[y][threadIdx.x] + g_part[y][threadIdx.x + 32];
        for (int o = 16; o; o >>= 1) d += __shfl_xor_sync(0xffffffffu, d, o);
        if (threadIdx.x == 0) {
            float m = (float)(d * (1.0 / (double)WELEM)) + 1e-5f;
            s_sc = m;
            g_scale[y] = m;
        }
    }
    __syncthreads();
    const float sc = s_sc;
    const int n4 = WELEM / 4;
    for (int i = blockIdx.x * blockDim.x + threadIdx.x; i < n4; i += gridDim.x * blockDim.x) {
        float4 v = ((const float4*)w)[i];
        float r0 = fminf(1.f, fmaxf(-1.f, rintf(__fdiv_rn(v.x, sc))));
        float r1 = fminf(1.f, fmaxf(-1.f, rintf(__fdiv_rn(v.y, sc))));
        float r2 = fminf(1.f, fmaxf(-1.f, rintf(__fdiv_rn(v.z, sc))));
        float r3 = fminf(1.f, fmaxf(-1.f, rintf(__fdiv_rn(v.w, sc))));
        unsigned int lo = ((unsigned int)__bfloat16_as_ushort(__float2bfloat16_rn(r1)) << 16)
                        | (unsigned int)__bfloat16_as_ushort(__float2bfloat16_rn(r0));
        unsigned int hi = ((unsigned int)__bfloat16_as_ushort(__float2bfloat16_rn(r3)) << 16)
                        | (unsigned int)__bfloat16_as_ushort(__float2bfloat16_rn(r2));
        ((uint2*)q)[i] = make_uint2(lo, hi);
    }
}

// ------------------------- wmma bf16 GEMM, 3 planes ------------------------
// C[M][N] = sum_s A_s[M][K] @ B[N][K]^T. 128x128 CTA, BK=16, double-buffered.
__global__ __launch_bounds__(256) void k_bgemm3(const __nv_bfloat16* __restrict__ A,
                                                const __nv_bfloat16* __restrict__ B,
                                                float* __restrict__ C) {
    __shared__ __align__(16) __nv_bfloat16 sm[2][4][128 * 24];
    const int t = threadIdx.x;
    const int wid = t >> 5;
    const int wm = (wid >> 1) * 32;
    const int wn = (wid & 1) * 64;
    const int lrow = t >> 1;
    const int lcol = (t & 1) * 8;
    const __nv_bfloat16* ag = A + ((size_t)blockIdx.y * 128 + lrow) * HID + lcol;
    const __nv_bfloat16* bg = B + ((size_t)blockIdx.x * 128 + lrow) * HID + lcol;

    wx::fragment<wx::accumulator, 16, 16, 16, float> acc[2][4];
    #pragma unroll
    for (int i = 0; i < 2; i++)
        #pragma unroll
        for (int j = 0; j < 4; j++)
            wx::fill_fragment(acc[i][j], 0.0f);

    uint4 ra0 = *(const uint4*)(ag + 0 * PLANE);
    uint4 ra1 = *(const uint4*)(ag + 1 * PLANE);
    uint4 ra2 = *(const uint4*)(ag + 2 * PLANE);
    uint4 rb  = *(const uint4*)bg;
    *(uint4*)&sm[0][0][lrow * 24 + lcol] = ra0;
    *(uint4*)&sm[0][1][lrow * 24 + lcol] = ra1;
    *(uint4*)&sm[0][2][lrow * 24 + lcol] = ra2;
    *(uint4*)&sm[0][3][lrow * 24 + lcol] = rb;
    __syncthreads();

    #pragma unroll 1
    for (int it = 0; it < 64; ++it) {
        const int cur = it & 1;
        if (it < 63) {
            const int k0 = (it + 1) * 16;
            ra0 = *(const uint4*)(ag + 0 * PLANE + k0);
            ra1 = *(const uint4*)(ag + 1 * PLANE + k0);
            ra2 = *(const uint4*)(ag + 2 * PLANE + k0);
            rb  = *(const uint4*)(bg + k0);
        }
        wx::fragment<wx::matrix_b, 16, 16, 16, __nv_bfloat16, wx::col_major> bf[4];
        #pragma unroll
        for (int j = 0; j < 4; j++)
            wx::load_matrix_sync(bf[j], &sm[cur][3][(wn + 16 * j) * 24], 24);
        #pragma unroll
        for (int s = 0; s < 3; s++) {
            wx::fragment<wx::matrix_a, 16, 16, 16, __nv_bfloat16, wx::row_major> af[2];
            wx::load_matrix_sync(af[0], &sm[cur][s][(wm) * 24], 24);
            wx::load_matrix_sync(af[1], &sm[cur][s][(wm + 16) * 24], 24);
            #pragma unroll
            for (int i = 0; i < 2; i++)
                #pragma unroll
                for (int j = 0; j < 4; j++)
                    wx::mma_sync(acc[i][j], af[i], bf[j], acc[i][j]);
        }
        if (it < 63) {
            const int nxt = cur ^ 1;
            *(uint4*)&sm[nxt][0][lrow * 24 + lcol] = ra0;
            *(uint4*)&sm[nxt][1][lrow * 24 + lcol] = ra1;
            *(uint4*)&sm[nxt][2][lrow * 24 + lcol] = ra2;
            *(uint4*)&sm[nxt][3][lrow * 24 + lcol] = rb;
            __syncthreads();
        }
    }

    #pragma unroll
    for (int i = 0; i < 2; i++)
        #pragma unroll
        for (int j = 0; j < 4; j++) {
            float* cp = C + ((size_t)blockIdx.y * 128 + wm + 16 * i) * HID
                          + blockIdx.x * 128 + wn + 16 * j;
            wx::store_matrix_sync(cp, acc[i][j], HID, wx::mem_row_major);
        }
}

// Same with 2 planes (V and O projections; residual ~2^-17 is negligible).
__global__ __launch_bounds__(256) void k_bgemm2(const __nv_bfloat16* __restrict__ A,
                                                const __nv_bfloat16* __restrict__ B,
                                                float* __restrict__ C) {
    __shared__ __align__(16) __nv_bfloat16 sm[2][3][128 * 24];
    const int t = threadIdx.x;
    const int wid = t >> 5;
    const int wm = (wid >> 1) * 32;
    const int wn = (wid & 1) * 64;
    const int lrow = t >> 1;
    const int lcol = (t & 1) * 8;
    const __nv_bfloat16* ag = A + ((size_t)blockIdx.y * 128 + lrow) * HID + lcol;
    const __nv_bfloat16* bg = B + ((size_t)blockIdx.x * 128 + lrow) * HID + lcol;

    wx::fragment<wx::accumulator, 16, 16, 16, float> acc[2][4];
    #pragma unroll
    for (int i = 0; i < 2; i++)
        #pragma unroll
        for (int j = 0; j < 4; j++)
            wx::fill_fragment(acc[i][j], 0.0f);

    uint4 ra0 = *(const uint4*)(ag + 0 * PLANE);
    uint4 ra1 = *(const uint4*)(ag + 1 * PLANE);
    uint4 rb  = *(const uint4*)bg;
    *(uint4*)&sm[0][0][lrow * 24 + lcol] = ra0;
    *(uint4*)&sm[0][1][lrow * 24 + lcol] = ra1;
    *(uint4*)&sm[0][2][lrow * 24 + lcol] = rb;
    __syncthreads();

    #pragma unroll 1
    for (int it = 0; it < 64; ++it) {
        const int cur = it & 1;
        if (it < 63) {
            const int k0 = (it + 1) * 16;
            ra0 = *(const uint4*)(ag + 0 * PLANE + k0);
            ra1 = *(const uint4*)(ag + 1 * PLANE + k0);
            rb  = *(const uint4*)(bg + k0);
        }
        wx::fragment<wx::matrix_b, 16, 16, 16, __nv_bfloat16, wx::col_major> bf[4];
        #pragma unroll
        for (int j = 0; j < 4; j++)
            wx::load_matrix_sync(bf[j], &sm[cur][2][(wn + 16 * j) * 24], 24);
        #pragma unroll
        for (int s = 0; s < 2; s++) {
            wx::fragment<wx::matrix_a, 16, 16, 16, __nv_bfloat16, wx::row_major> af[2];
            wx::load_matrix_sync(af[0], &sm[cur][s][(wm) * 24], 24);
            wx::load_matrix_sync(af[1], &sm[cur][s][(wm + 16) * 24], 24);
            #pragma unroll
            for (int i = 0; i < 2; i++)
                #pragma unroll
                for (int j = 0; j < 4; j++)
                    wx::mma_sync(acc[i][j], af[i], bf[j], acc[i][j]);
        }
        if (it < 63) {
            const int nxt = cur ^ 1;
            *(uint4*)&sm[nxt][0][lrow * 24 + lcol] = ra0;
            *(uint4*)&sm[nxt][1][lrow * 24 + lcol] = ra1;
            *(uint4*)&sm[nxt][2][lrow * 24 + lcol] = rb;
            __syncthreads();
        }
    }

    #pragma unroll
    for (int i = 0; i < 2; i++)
        #pragma unroll
        for (int j = 0; j < 4; j++) {
            float* cp = C + ((size_t)blockIdx.y * 128 + wm + 16 * i) * HID
                          + blockIdx.x * 128 + wn + 16 * j;
            wx::store_matrix_sync(cp, acc[i][j], HID, wx::mem_row_major);
        }
}

// ------------------------- trig table --------------------------------------
__global__ __launch_bounds__(256) void k_trig() {
    int idx = blockIdx.x * blockDim.x + threadIdx.x;
    if (idx >= Ssz * 32) return;
    int pos = idx >> 5;
    int d2  = idx & 31;
    float e = (float)(2 * d2) / 64.0f;
    float t = (float)pow(10000.0, (double)e);
    float invf = __frcp_rn(t);
    float f = __fmul_rn((float)pos, invf);
    double sd, cd;
    sincos((double)f, &sd, &cd);
    g_cos[idx] = (float)cd;
    g_sin[idx] = (float)sd;
}

// ------------------------- RoPE + exact 3-plane split of q,k ----------------
__global__ __launch_bounds__(256) void k_rope(const int* __restrict__ pos_ids) {
    int idx = blockIdx.x * blockDim.x + threadIdx.x;
    if (idx >= MROWS * NH * 32) return;
    int m  = idx >> 9;
    int hp = idx & 511;
    int h  = hp >> 5;
    int d2 = hp & 31;
    int p = pos_ids[m];
    p = (p < 0) ? 0 : ((p >= Ssz) ? Ssz - 1 : p);
    float cs = g_cos[p * 32 + d2];
    float sn = g_sin[p * 32 + d2];
    size_t base = (size_t)m * HID + h * HD + d2;
    float q1 = g_qkv[base], q2 = g_qkv[base + 32];
    float k1 = g_qkv[PLANE + base], k2 = g_qkv[PLANE + base + 32];
    float qa = q1 * cs - q2 * sn;
    float qb = q2 * cs + q1 * sn;
    float ka = k1 * cs - k2 * sn;
    float kb = k2 * cs + k1 * sn;
    float vals[4];
    vals[0] = qa; vals[1] = qb; vals[2] = ka; vals[3] = kb;
    #pragma unroll
    for (int e = 0; e < 4; e++) {
        float xv = vals[e];
        __nv_bfloat16 h0 = __float2bfloat16_rn(xv);
        float r1 = __fsub_rn(xv, __bfloat162float(h0));
        __nv_bfloat16 h1 = __float2bfloat16_rn(r1);
        float r2 = __fsub_rn(r1, __bfloat162float(h1));
        __nv_bfloat16 h2 = __float2bfloat16_rn(r2);
        __nv_bfloat16* dst = (e < 2) ? g_qpl : g_kpl;
        size_t a = base + ((e & 1) ? 32 : 0);
        dst[0 * PLANE + a] = h0;
        dst[1 * PLANE + a] = h1;
        dst[2 * PLANE + a] = h2;
    }
}

// ------------------------- attention ---------------------------------------
// Scores via wmma on exact bf16 planes (6 terms, si+sj<=2); softmax + P*V fp32.
// Q tile 64, K tile 32. Shared memory (bytes):
//   Q01 [2][64][72] bf16  at 0      (18432)
//   Q2  [64][64]   bf16   at 18432  (8192)
//   Ks  [3][32][72] bf16  at 26624  (13824)   <- Ps [64][36] f32 aliases here
//   Vs  [32][64]   f32    at 40448  (8192)    total 48640
__global__ __launch_bounds__(256) void k_attn() {
    __shared__ __align__(16) char smb[48640];
    __nv_bfloat16* q01 = (__nv_bfloat16*)(smb);
    __nv_bfloat16* q2  = (__nv_bfloat16*)(smb + 18432);
    __nv_bfloat16* ksm = (__nv_bfloat16*)(smb + 26624);
    float* ps = (float*)(smb + 26624);
    float* vs = (float*)(smb + 40448);
    const float* Vg = g_qkv + 2 * PLANE;

    const int tid = threadIdx.x;
    const int wid = tid >> 5;
    const int b = blockIdx.y >> 4;
    const int h = blockIdx.y & 15;
    const int q0 = blockIdx.x * 64;
    const size_t rowbase = (size_t)b * Ssz * HID + (size_t)h * HD;

    // load Q planes
    for (int idx = tid; idx < 64 * 16; idx += 256) {
        int r = idx >> 4;
        int c4 = (idx & 15) * 4;
        size_t g = rowbase + (size_t)(q0 + r) * HID + c4;
        *(uint2*)(q01 + r * 72 + c4)        = *(const uint2*)(g_qpl + 0 * PLANE + g);
        *(uint2*)(q01 + (64 + r) * 72 + c4) = *(const uint2*)(g_qpl + 1 * PLANE + g);
        *(uint2*)(q2 + r * 64 + c4)         = *(const uint2*)(g_qpl + 2 * PLANE + g);
    }

    const int ty = tid >> 4, tx = tid & 15;
    const int i0 = ty << 2;
    const int cj = tx << 2;
    const int j0 = tx << 1;
    const int wr = wid >> 1;
    const int wc = wid & 1;

    float m_i[4], l_i[4], o[4][4];
    #pragma unroll
    for (int i = 0; i < 4; i++) {
        m_i[i] = -3.0e38f; l_i[i] = 0.f;
        #pragma unroll
        for (int d = 0; d < 4; d++) o[i][d] = 0.f;
    }

    for (int kt = 0; kt < Ssz; kt += 32) {
        __syncthreads();
        for (int idx = tid; idx < 32 * 16; idx += 256) {
            int r = idx >> 4;
            int c4 = (idx & 15) * 4;
            size_t g = rowbase + (size_t)(kt + r) * HID + c4;
            *(uint2*)(ksm + (r) * 72 + c4)       = *(const uint2*)(g_kpl + 0 * PLANE + g);
            *(uint2*)(ksm + (32 + r) * 72 + c4)  = *(const uint2*)(g_kpl + 1 * PLANE + g);
            *(uint2*)(ksm + (64 + r) * 72 + c4)  = *(const uint2*)(g_kpl + 2 * PLANE + g);
            *(float4*)(vs + r * 64 + c4)         = *(const float4*)(Vg + g);
        }
        __syncthreads();

        // scores S = sum over (si,sj), si+sj<=2, of Qsi @ Ksj^T
        wx::fragment<wx::accumulator, 16, 16, 16, float> sacc;
        wx::fill_fragment(sacc, 0.0f);
        #pragma unroll
        for (int si = 0; si < 3; si++) {
            wx::fragment<wx::matrix_a, 16, 16, 16, __nv_bfloat16, wx::row_major> af[4];
            #pragma unroll
            for (int kk = 0; kk < 4; kk++) {
                if (si < 2)
                    wx::load_matrix_sync(af[kk], q01 + (si * 64 + wr * 16) * 72 + kk * 16, 72);
                else
                    wx::load_matrix_sync(af[kk], q2 + (wr * 16) * 64 + kk * 16, 64);
            }
            const int sjmax = 3 - si;
            #pragma unroll
            for (int sj = 0; sj < 3; sj++) {
                if (sj < sjmax) {
                    #pragma unroll
                    for (int kk = 0; kk < 4; kk++) {
                        wx::fragment<wx::matrix_b, 16, 16, 16, __nv_bfloat16, wx::col_major> bfr;
                        wx::load_matrix_sync(bfr, ksm + (sj * 32 + wc * 16) * 72 + kk * 16, 72);
                        wx::mma_sync(sacc, af[kk], bfr, sacc);
                    }
                }
            }
        }
        __syncthreads();
        wx::store_matrix_sync(ps + (wr * 16) * 36 + wc * 16, sacc, 36, wx::mem_row_major);
        __syncthreads();

        // softmax (fp32, identical numerics to the passing fp32 kernel)
        #pragma unroll
        for (int i = 0; i < 4; i++) {
            float s0 = ps[(i0 + i) * 36 + j0] * 0.125f;
            float s1 = ps[(i0 + i) * 36 + j0 + 1] * 0.125f;
            float mx = fmaxf(s0, s1);
            #pragma unroll
            for (int off = 8; off; off >>= 1)
                mx = fmaxf(mx, __shfl_xor_sync(0xffffffffu, mx, off));
            float mnew = fmaxf(m_i[i], mx);
            float corr = __expf(m_i[i] - mnew);
            float p0 = __expf(s0 - mnew), p1 = __expf(s1 - mnew);
            float rs = p0 + p1;
            #pragma unroll
            for (int off = 8; off; off >>= 1)
                rs += __shfl_xor_sync(0xffffffffu, rs, off);
            l_i[i] = l_i[i] * corr + rs;
            m_i[i] = mnew;
            #pragma unroll
            for (int d = 0; d < 4; d++) o[i][d] *= corr;
            ps[(i0 + i) * 36 + j0] = p0;
            ps[(i0 + i) * 36 + j0 + 1] = p1;
        }
        __syncthreads();

        // P @ V (fp32)
        #pragma unroll
        for (int j = 0; j < 32; j += 4) {
            float4 pv0 = *(const float4*)(ps + (i0 + 0) * 36 + j);
            float4 pv1 = *(const float4*)(ps + (i0 + 1) * 36 + j);
            float4 pv2 = *(const float4*)(ps + (i0 + 2) * 36 + j);
            float4 pv3 = *(const float4*)(ps + (i0 + 3) * 36 + j);
            float4 vv0 = *(const float4*)(vs + (j + 0) * 64 + cj);
            float4 vv1 = *(const float4*)(vs + (j + 1) * 64 + cj);
            float4 vv2 = *(const float4*)(vs + (j + 2) * 64 + cj);
            float4 vv3 = *(const float4*)(vs + (j + 3) * 64 + cj);
            o[0][0] += pv0.x*vv0.x + pv0.y*vv1.x + pv0.z*vv2.x + pv0.w*vv3.x;
            o[0][1] += pv0.x*vv0.y + pv0.y*vv1.y + pv0.z*vv2.y + pv0.w*vv3.y;
            o[0][2] += pv0.x*vv0.z + pv0.y*vv1.z + pv0.z*vv2.z + pv0.w*vv3.z;
            o[0][3] += pv0.x*vv0.w + pv0.y*vv1.w + pv0.z*vv2.w + pv0.w*vv3.w;
            o[1][0] += pv1.x*vv0.x + pv1.y*vv1.x + pv1.z*vv2.x + pv1.w*vv3.x;
            o[1][1] += pv1.x*vv0.y + pv1.y*vv1.y + pv1.z*vv2.y + pv1.w*vv3.y;
            o[1][2] += pv1.x*vv0.z + pv1.y*vv1.z + pv1.z*vv2.z + pv1.w*vv3.z;
            o[1][3] += pv1.x*vv0.w + pv1.y*vv1.w + pv1.z*vv2.w + pv1.w*vv3.w;
            o[2][0] += pv2.x*vv0.x + pv2.y*vv1.x + pv2.z*vv2.x + pv2.w*vv3.x;
            o[2][1] += pv2.x*vv0.y + pv2.y*vv1.y + pv2.z*vv2.y + pv2.w*vv3.y;
            o[2][2] += pv2.x*vv0.z + pv2.y*vv1.z + pv2.z*vv2.z + pv2.w*vv3.z;
            o[2][3] += pv2.x*vv0.w + pv2.y*vv1.w + pv2.z*vv2.w + pv2.w*vv3.w;
            o[3][0] += pv3.x*vv0.x + pv3.y*vv1.x + pv3.z*vv2.x + pv3.w*vv3.x;
            o[3][1] += pv3.x*vv0.y + pv3.y*vv1.y + pv3.z*vv2.y + pv3.w*vv3.y;
            o[3][2] += pv3.x*vv0.z + pv3.y*vv1.z + pv3.z*vv2.z + pv3.w*vv3.z;
            o[3][3] += pv3.x*vv0.w + pv3.y*vv1.w + pv3.z*vv2.w + pv3.w*vv3.w;
        }
    }
    #pragma unroll
    for (int i = 0; i < 4; i++) {
        float inv = 1.0f / l_i[i];
        float4 w = make_float4(o[i][0]*inv, o[i][1]*inv, o[i][2]*inv, o[i][3]*inv);
        *(float4*)(g_ctx + rowbase + (size_t)(q0 + i0 + i) * HID + cj) = w;
    }
}

// ------------------------- out_scale ---------------------------------------
__global__ void k_out_scale(const float* __restrict__ hss, float* __restrict__ out, int out_size) {
    if (out_size >= MROWS * HID + 1) {
        out[MROWS * HID] = (hss[0] * g_scale[2]) * g_scale[3];
    }
}

// ------------------------- launch ------------------------------------------
extern "C" void kernel_launch(void* const* d_in, const int* in_sizes, int n_in,
                              void* d_out, int out_size) {
    const float* hs  = (const float*)d_in[0];
    const float* hss = (const float*)d_in[1];
    const int*   pos = (const int*)d_in[2];
    const float* wq  = (const float*)d_in[3];
    const float* wk  = (const float*)d_in[4];
    const float* wv  = (const float*)d_in[5];
    const float* wo  = (const float*)d_in[6];
    float* out = (float*)d_out;

    __nv_bfloat16 *p_wb, *p_pl;
    float *p_qkv, *p_ctx;
    cudaGetSymbolAddress((void**)&p_wb,  g_wb);
    cudaGetSymbolAddress((void**)&p_pl,  g_pl);
    cudaGetSymbolAddress((void**)&p_qkv, g_qkv);
    cudaGetSymbolAddress((void**)&p_ctx, g_ctx);

    float* qf = p_qkv + 0 * PLANE;
    float* kf = p_qkv + 1 * PLANE;
    float* vf = p_qkv + 2 * PLANE;

    k_abssum<<<dim3(64, 4), 256>>>(wq, wk, wv, wo);
    k_split<<<(MROWS * HID / 4 + 255) / 256, 256>>>(hs);
    k_quant<<<dim3(64, 4), 256>>>(wq, wk, wv, wo);

    dim3 gproj(HID / 128, MROWS / 128);
    k_bgemm3<<<gproj, 256>>>(p_pl, p_wb + 0 * (size_t)WELEM, qf);
    k_bgemm3<<<gproj, 256>>>(p_pl, p_wb + 1 * (size_t)WELEM, kf);
    k_bgemm2<<<gproj, 256>>>(p_pl, p_wb + 2 * (size_t)WELEM, vf);

    k_trig<<<(Ssz * 32 + 255) / 256, 256>>>();
    k_rope<<<(MROWS * NH * 32 + 255) / 256, 256>>>(pos);

    k_attn<<<dim3(Ssz / 64, Bsz * NH), 256>>>();

    k_split<<<(MROWS * HID / 4 + 255) / 256, 256>>>(p_ctx);
    k_bgemm2<<<gproj, 256>>>(p_pl, p_wb + 3 * (size_t)WELEM, out);

    k_out_scale<<<1, 1>>>(hss, out, out_size);
}